// round 9
// baseline (speedup 1.0000x reference)
#include <cuda_runtime.h>
#include <cuda_bf16.h>

// ---------------------------------------------------------------------------
// Single fused kernel. One block of 256 threads per (batch b, type v, slice):
//   - scan slice's i-range for rows with z_i == v  (<= ~8 rows)
//   - prefactor pref[r] = sum_a emb[v,a]*time_rbf(t_b,a)*W[a,r]
//   - sample phi(d) at 2*KNOTS+1 points, fit piecewise quadratic
//     (global form A + B*d + C*d^2) into a small smem table
//   - pair phase: each thread holds 4 j-positions in REGISTERS loaded
//     directly from gmem (coalesced LDG.128, L2-hot); block-wide row loop,
//     warp-shfl reduce + fixed-order 8-partial combine (deterministic)
// No position staging to smem at all.
// ---------------------------------------------------------------------------
#define KNOTS  64
#define DMAXF  16.0f
#define SLICES 8
#define TPB    256
#define NWARPS (TPB / 32)
#define RPASS  8
#define MAXROWS 96

__device__ __forceinline__ float ex2f_fast(float x) {
    float y; asm("ex2.approx.ftz.f32 %0, %1;" : "=f"(y) : "f"(x)); return y;
}
__device__ __forceinline__ float sqrtf_fast(float x) {
    float y; asm("sqrt.approx.f32 %0, %1;" : "=f"(y) : "f"(x)); return y;
}

template <int RR>
__global__ __launch_bounds__(TPB)
void vf_fused_kernel(const float* __restrict__ pos,
                     const int*   __restrict__ z,
                     const float* __restrict__ t,
                     const float* __restrict__ emb,
                     const float* __restrict__ W,
                     const float* __restrict__ r_off,
                     const float* __restrict__ r_wid,
                     const float* __restrict__ t_off,
                     const float* __restrict__ t_wid,
                     float*       __restrict__ out,
                     int N, int A, int R, int MAXZ) {
    __shared__ float4 s_tab[KNOTS];
    __shared__ float  s_phi[2 * KNOTS + 1];
    __shared__ float  sx[128];
    __shared__ float  s_pref[64], s_k2[64], s_off[64];
    __shared__ int    s_rows[MAXROWS];
    __shared__ float  s_part[RPASS][NWARPS][3];
    __shared__ int    s_count;

    const float LOG2E = 1.4426950408889634f;
    int bvs   = blockIdx.x;
    int bv    = bvs / SLICES;
    int slice = bvs % SLICES;
    int b     = bv / MAXZ;
    int v     = bv % MAXZ;
    int tid   = threadIdx.x;
    int Ruse  = (RR > 0) ? RR : R;
    int Rpad  = (Ruse + 3) & ~3;

    if (tid == 0) s_count = 0;
    __syncthreads();

    const float* posb = pos + (size_t)b * N * 3;

    // ---- scan slice's i-range ----
    int lo = (int)(((long long)N * slice) / SLICES);
    int hi = (int)(((long long)N * (slice + 1)) / SLICES);
    for (int i = lo + tid; i < hi; i += TPB) {
        if (__ldg(&z[i]) == v) {
            int idx = atomicAdd(&s_count, 1);
            if (idx < MAXROWS) s_rows[idx] = i;
        }
    }

    // ---- small param prep (overlaps scan) ----
    if (tid < A && tid < 128) {
        float tw = t_wid[tid];
        float dt = t[b] - t_off[tid];
        float c  = (-0.5f / (tw * tw)) * LOG2E;
        sx[tid] = emb[(size_t)v * A + tid] * ex2f_fast(c * dt * dt);
    }
    if (tid < 64) {
        if (tid < Ruse) {
            float w = r_wid[tid];
            s_k2[tid]  = (-0.5f / (w * w)) * LOG2E;
            s_off[tid] = r_off[tid];
        } else {
            s_k2[tid]  = -1.0f;     // padding: pref stays 0 -> inert
            s_off[tid] = 0.0f;
            s_pref[tid] = 0.0f;
        }
    }
    __syncthreads();

    int count = s_count;
    if (count == 0) return;          // uniform across block
    if (count > MAXROWS) count = MAXROWS;

    // ---- load this thread's 4 j-positions straight from gmem (coalesced:
    //      thread t reads floats [12t, 12t+12) = points [4t, 4t+4)) ----
    float jpx[4], jpy[4], jpz[4];
    {
        int base = tid * 12;             // covers N <= 4*TPB points
        if (base + 12 <= 3 * N) {
            float4 q0 = __ldg((const float4*)(posb + base));
            float4 q1 = __ldg((const float4*)(posb + base + 4));
            float4 q2 = __ldg((const float4*)(posb + base + 8));
            jpx[0] = q0.x; jpy[0] = q0.y; jpz[0] = q0.z;
            jpx[1] = q0.w; jpy[1] = q1.x; jpz[1] = q1.y;
            jpx[2] = q1.z; jpy[2] = q1.w; jpz[2] = q2.x;
            jpx[3] = q2.y; jpy[3] = q2.z; jpz[3] = q2.w;
        } else {
#pragma unroll
            for (int q = 0; q < 4; q++) {
                int j = 4 * tid + q;
                int jj = (j < N) ? j : 0;
                jpx[q] = __ldg(&posb[3 * jj + 0]);
                jpy[q] = __ldg(&posb[3 * jj + 1]);
                jpz[q] = __ldg(&posb[3 * jj + 2]);
            }
        }
    }

    // ---- prefactor: 4 threads per r ----
    {
        int rr  = tid >> 2;
        int sub = tid & 3;
        int rc  = (rr < Ruse) ? rr : (Ruse - 1);
        float s = 0.0f;
        for (int a = sub; a < A; a += 4)
            s = fmaf(sx[a], __ldg(&W[(size_t)a * R + rc]), s);
        s += __shfl_xor_sync(0xFFFFFFFFu, s, 1);
        s += __shfl_xor_sync(0xFFFFFFFFu, s, 2);
        if (sub == 0 && rr < Ruse) s_pref[rr] = s;
    }
    __syncthreads();

    // ---- sample phi at 2*KNOTS+1 points (padded, branch-free) ----
    const float hh = DMAXF / (float)KNOTS;
    for (int p = tid; p < 2 * KNOTS + 1; p += TPB) {
        float d = (float)p * (0.5f * hh);
        float a0 = 0.f, a1 = 0.f, a2 = 0.f, a3 = 0.f;
#pragma unroll 1
        for (int r = 0; r < Rpad; r += 4) {
            float e0 = d - s_off[r + 0];
            float e1 = d - s_off[r + 1];
            float e2 = d - s_off[r + 2];
            float e3 = d - s_off[r + 3];
            a0 = fmaf(s_pref[r + 0], ex2f_fast(s_k2[r + 0] * e0 * e0), a0);
            a1 = fmaf(s_pref[r + 1], ex2f_fast(s_k2[r + 1] * e1 * e1), a1);
            a2 = fmaf(s_pref[r + 2], ex2f_fast(s_k2[r + 2] * e2 * e2), a2);
            a3 = fmaf(s_pref[r + 3], ex2f_fast(s_k2[r + 3] * e3 * e3), a3);
        }
        s_phi[p] = (a0 + a1) + (a2 + a3);
    }
    __syncthreads();

    // ---- fit quadratics (global form A + B*d + C*d^2) ----
    if (tid < KNOTS) {
        float y0 = s_phi[2 * tid + 0];
        float ym = s_phi[2 * tid + 1];
        float y1 = s_phi[2 * tid + 2];
        float inv_h = 1.0f / hh;
        float d0 = (float)tid * hh;
        float bl = (4.0f * ym - 3.0f * y0 - y1) * inv_h;
        float cl = 2.0f * (y1 - 2.0f * ym + y0) * (inv_h * inv_h);
        float Cg = cl;
        float Bg = bl - 2.0f * cl * d0;
        float Ag = y0 - bl * d0 + cl * d0 * d0;
        s_tab[tid] = make_float4(Ag, Bg, Cg, 0.0f);
    }
    __syncthreads();

    // ---- pair phase: block-wide per row, j's from registers ----
    const float inv_h  = (float)KNOTS / DMAXF;
    const float dclamp = DMAXF - 0.5f * hh;
    int warp = tid >> 5, lane = tid & 31;

    for (int p0 = 0; p0 < count; p0 += RPASS) {
        int prn = count - p0; if (prn > RPASS) prn = RPASS;

        for (int pr = 0; pr < prn; pr++) {
            int i = s_rows[p0 + pr];
            float pix = __ldg(&posb[3 * i + 0]);   // broadcast loads
            float piy = __ldg(&posb[3 * i + 1]);
            float piz = __ldg(&posb[3 * i + 2]);

            float a0 = 0.f, a1 = 0.f, a2 = 0.f;
#pragma unroll
            for (int q = 0; q < 4; q++) {
                int j = 4 * tid + q;
                if (j < N) {
                    float rx = pix - jpx[q];
                    float ry = piy - jpy[q];
                    float rz = piz - jpz[q];
                    float d2 = fmaf(rx, rx, fmaf(ry, ry, fmaf(rz, rz, 1e-6f)));
                    float d  = fminf(sqrtf_fast(d2), dclamp);
                    int   k  = (int)(d * inv_h);
                    float4 c = s_tab[k];
                    float phi = fmaf(fmaf(c.z, d, c.y), d, c.x);
                    a0 = fmaf(phi, rx, a0);
                    a1 = fmaf(phi, ry, a1);
                    a2 = fmaf(phi, rz, a2);
                }
            }
            // generic tail (N > 4*TPB): read gmem directly
            for (int j = 4 * TPB + tid; j < N; j += TPB) {
                float rx = pix - __ldg(&posb[3 * j + 0]);
                float ry = piy - __ldg(&posb[3 * j + 1]);
                float rz = piz - __ldg(&posb[3 * j + 2]);
                float d2 = fmaf(rx, rx, fmaf(ry, ry, fmaf(rz, rz, 1e-6f)));
                float d  = fminf(sqrtf_fast(d2), dclamp);
                int   k  = (int)(d * inv_h);
                float4 c = s_tab[k];
                float phi = fmaf(fmaf(c.z, d, c.y), d, c.x);
                a0 = fmaf(phi, rx, a0);
                a1 = fmaf(phi, ry, a1);
                a2 = fmaf(phi, rz, a2);
            }
#pragma unroll
            for (int off = 16; off > 0; off >>= 1) {
                a0 += __shfl_down_sync(0xFFFFFFFFu, a0, off);
                a1 += __shfl_down_sync(0xFFFFFFFFu, a1, off);
                a2 += __shfl_down_sync(0xFFFFFFFFu, a2, off);
            }
            if (lane == 0) {
                s_part[pr][warp][0] = a0;
                s_part[pr][warp][1] = a1;
                s_part[pr][warp][2] = a2;
            }
        }
        __syncthreads();

        if (tid < prn) {
            int i = s_rows[p0 + tid];
            float r0 = 0.f, r1 = 0.f, r2 = 0.f;
#pragma unroll
            for (int w = 0; w < NWARPS; w++) {
                r0 += s_part[tid][w][0];
                r1 += s_part[tid][w][1];
                r2 += s_part[tid][w][2];
            }
            size_t o = ((size_t)b * N + i) * 3;
            out[o + 0] = r0 + __ldg(&posb[3 * i + 0]);
            out[o + 1] = r1 + __ldg(&posb[3 * i + 1]);
            out[o + 2] = r2 + __ldg(&posb[3 * i + 2]);
        }
        __syncthreads();   // s_part reused next pass
    }
}

// ---------------------------------------------------------------------------
// Inputs (metadata order):
//  0 positions [B,N,3] f32, 1 t [B] f32, 2 z [N] i32, 3 emb [MAXZ,A] f32,
//  4 W [A,R] f32, 5 rad_off [R], 6 rad_wid [R], 7 time_off [A], 8 time_wid [A]
// ---------------------------------------------------------------------------
extern "C" void kernel_launch(void* const* d_in, const int* in_sizes, int n_in,
                              void* d_out, int out_size) {
    const float* positions = (const float*)d_in[0];
    const float* t         = (const float*)d_in[1];
    const int*   z         = (const int*)  d_in[2];
    const float* emb       = (const float*)d_in[3];
    const float* W         = (const float*)d_in[4];
    const float* r_off     = (const float*)d_in[5];
    const float* r_wid     = (const float*)d_in[6];
    const float* t_off     = (const float*)d_in[7];
    const float* t_wid     = (const float*)d_in[8];

    int B    = in_sizes[1];
    int N    = in_sizes[2];
    int R    = in_sizes[5];
    int A    = in_sizes[7];
    int MAXZ = in_sizes[3] / A;

    int grid = B * MAXZ * SLICES;

    if (R == 50)
        vf_fused_kernel<50><<<grid, TPB>>>(
            positions, z, t, emb, W, r_off, r_wid, t_off, t_wid,
            (float*)d_out, N, A, R, MAXZ);
    else
        vf_fused_kernel<0><<<grid, TPB>>>(
            positions, z, t, emb, W, r_off, r_wid, t_off, t_wid,
            (float*)d_out, N, A, R, MAXZ);
}

// round 11
// speedup vs baseline: 1.2182x; 1.2182x over previous
#include <cuda_runtime.h>
#include <cuda_bf16.h>

// ---------------------------------------------------------------------------
// Single fused kernel. One block of 256 threads per (batch b, type v, slice):
//   - scan slice's i-range for rows with z_i == v
//   - prefactor pref[r] = sum_a emb[v,a]*time_rbf(t_b,a)*W[a,r]
//   - sample phi(d) at 2*KNOTS+1 points, fit piecewise quadratic
//     (global form A + B*d + C*d^2) into a small smem table
//   - pair phase: each thread holds 4 j-positions in REGISTERS loaded
//     directly from gmem (coalesced, L2-hot); block-wide row loop,
//     warp-shfl reduce + fixed-order 8-partial combine (deterministic)
// NOTE: every __shfl_*_sync uses full mask and is executed by ALL lanes of
// the participating warps unconditionally (R10 hang postmortem).
// ---------------------------------------------------------------------------
#define KNOTS  32
#define DMAXF  16.0f
#define SLICES 4
#define TPB    256
#define NWARPS (TPB / 32)
#define RPASS  8
#define MAXROWS 128

__device__ __forceinline__ float ex2f_fast(float x) {
    float y; asm("ex2.approx.ftz.f32 %0, %1;" : "=f"(y) : "f"(x)); return y;
}
__device__ __forceinline__ float sqrtf_fast(float x) {
    float y; asm("sqrt.approx.f32 %0, %1;" : "=f"(y) : "f"(x)); return y;
}

template <int RR>
__global__ __launch_bounds__(TPB)
void vf_fused_kernel(const float* __restrict__ pos,
                     const int*   __restrict__ z,
                     const float* __restrict__ t,
                     const float* __restrict__ emb,
                     const float* __restrict__ W,
                     const float* __restrict__ r_off,
                     const float* __restrict__ r_wid,
                     const float* __restrict__ t_off,
                     const float* __restrict__ t_wid,
                     float*       __restrict__ out,
                     int N, int A, int R, int MAXZ) {
    __shared__ float4 s_tab[KNOTS];
    __shared__ float  s_phi[2 * KNOTS + 1];
    __shared__ float  sx[128];
    __shared__ float  s_pref[64], s_k2[64], s_off[64];
    __shared__ int    s_rows[MAXROWS];
    __shared__ float  s_part[RPASS][NWARPS][3];
    __shared__ int    s_count;

    const float LOG2E = 1.4426950408889634f;
    int bvs   = blockIdx.x;
    int bv    = bvs / SLICES;
    int slice = bvs % SLICES;
    int b     = bv / MAXZ;
    int v     = bv % MAXZ;
    int tid   = threadIdx.x;
    int Ruse  = (RR > 0) ? RR : R;
    int Rpad  = (Ruse + 3) & ~3;

    if (tid == 0) s_count = 0;
    __syncthreads();

    const float* posb = pos + (size_t)b * N * 3;

    // ---- scan slice's i-range ----
    int lo = (int)(((long long)N * slice) / SLICES);
    int hi = (int)(((long long)N * (slice + 1)) / SLICES);
    for (int i = lo + tid; i < hi; i += TPB) {
        if (__ldg(&z[i]) == v) {
            int idx = atomicAdd(&s_count, 1);
            if (idx < MAXROWS) s_rows[idx] = i;
        }
    }

    // ---- small param prep (overlaps scan) ----
    if (tid < A && tid < 128) {
        float tw = t_wid[tid];
        float dt = t[b] - t_off[tid];
        float c  = (-0.5f / (tw * tw)) * LOG2E;
        sx[tid] = emb[(size_t)v * A + tid] * ex2f_fast(c * dt * dt);
    }
    if (tid < 64) {
        if (tid < Ruse) {
            float w = r_wid[tid];
            s_k2[tid]  = (-0.5f / (w * w)) * LOG2E;
            s_off[tid] = r_off[tid];
        } else {
            s_k2[tid]  = -1.0f;     // padding: pref stays 0 -> inert
            s_off[tid] = 0.0f;
            s_pref[tid] = 0.0f;
        }
    }
    __syncthreads();

    int count = s_count;
    if (count == 0) return;          // uniform across block
    if (count > MAXROWS) count = MAXROWS;

    // ---- load this thread's 4 j-positions straight from gmem (coalesced:
    //      thread t reads floats [12t, 12t+12) = points [4t, 4t+4)) ----
    float jpx[4], jpy[4], jpz[4];
    {
        int base = tid * 12;
        if (base + 12 <= 3 * N) {
            float4 q0 = __ldg((const float4*)(posb + base));
            float4 q1 = __ldg((const float4*)(posb + base + 4));
            float4 q2 = __ldg((const float4*)(posb + base + 8));
            jpx[0] = q0.x; jpy[0] = q0.y; jpz[0] = q0.z;
            jpx[1] = q0.w; jpy[1] = q1.x; jpz[1] = q1.y;
            jpx[2] = q1.z; jpy[2] = q1.w; jpz[2] = q2.x;
            jpx[3] = q2.y; jpy[3] = q2.z; jpz[3] = q2.w;
        } else {
#pragma unroll
            for (int q = 0; q < 4; q++) {
                int j = 4 * tid + q;
                int jj = (j < N) ? j : 0;
                jpx[q] = __ldg(&posb[3 * jj + 0]);
                jpy[q] = __ldg(&posb[3 * jj + 1]);
                jpz[q] = __ldg(&posb[3 * jj + 2]);
            }
        }
    }

    // ---- prefactor: 4 threads per r (all lanes run the shfls) ----
    {
        int rr  = tid >> 2;
        int sub = tid & 3;
        int rc  = (rr < Ruse) ? rr : (Ruse - 1);
        float s = 0.0f;
        for (int a = sub; a < A; a += 4)
            s = fmaf(sx[a], __ldg(&W[(size_t)a * R + rc]), s);
        s += __shfl_xor_sync(0xFFFFFFFFu, s, 1);
        s += __shfl_xor_sync(0xFFFFFFFFu, s, 2);
        if (sub == 0 && rr < Ruse) s_pref[rr] = s;
    }
    __syncthreads();

    // ---- sample phi at 2*KNOTS+1 points (one thread per point) ----
    const float hh = DMAXF / (float)KNOTS;
    for (int p = tid; p < 2 * KNOTS + 1; p += TPB) {
        float d = (float)p * (0.5f * hh);
        float a0 = 0.f, a1 = 0.f, a2 = 0.f, a3 = 0.f;
#pragma unroll 1
        for (int r = 0; r < Rpad; r += 4) {
            float e0 = d - s_off[r + 0];
            float e1 = d - s_off[r + 1];
            float e2 = d - s_off[r + 2];
            float e3 = d - s_off[r + 3];
            a0 = fmaf(s_pref[r + 0], ex2f_fast(s_k2[r + 0] * e0 * e0), a0);
            a1 = fmaf(s_pref[r + 1], ex2f_fast(s_k2[r + 1] * e1 * e1), a1);
            a2 = fmaf(s_pref[r + 2], ex2f_fast(s_k2[r + 2] * e2 * e2), a2);
            a3 = fmaf(s_pref[r + 3], ex2f_fast(s_k2[r + 3] * e3 * e3), a3);
        }
        s_phi[p] = (a0 + a1) + (a2 + a3);
    }
    __syncthreads();

    // ---- fit quadratics (global form A + B*d + C*d^2) ----
    if (tid < KNOTS) {
        float y0 = s_phi[2 * tid + 0];
        float ym = s_phi[2 * tid + 1];
        float y1 = s_phi[2 * tid + 2];
        float inv_h = 1.0f / hh;
        float d0 = (float)tid * hh;
        float bl = (4.0f * ym - 3.0f * y0 - y1) * inv_h;
        float cl = 2.0f * (y1 - 2.0f * ym + y0) * (inv_h * inv_h);
        float Cg = cl;
        float Bg = bl - 2.0f * cl * d0;
        float Ag = y0 - bl * d0 + cl * d0 * d0;
        s_tab[tid] = make_float4(Ag, Bg, Cg, 0.0f);
    }
    __syncthreads();

    // ---- pair phase: block-wide per row, j's from registers ----
    const float inv_h  = (float)KNOTS / DMAXF;
    const float dclamp = DMAXF - 0.5f * hh;
    int warp = tid >> 5, lane = tid & 31;

    for (int p0 = 0; p0 < count; p0 += RPASS) {
        int prn = count - p0; if (prn > RPASS) prn = RPASS;

        for (int pr = 0; pr < prn; pr++) {
            int i = s_rows[p0 + pr];
            float pix = __ldg(&posb[3 * i + 0]);   // broadcast loads
            float piy = __ldg(&posb[3 * i + 1]);
            float piz = __ldg(&posb[3 * i + 2]);

            float a0 = 0.f, a1 = 0.f, a2 = 0.f;
#pragma unroll
            for (int q = 0; q < 4; q++) {
                int j = 4 * tid + q;
                if (j < N) {
                    float rx = pix - jpx[q];
                    float ry = piy - jpy[q];
                    float rz = piz - jpz[q];
                    float d2 = fmaf(rx, rx, fmaf(ry, ry, fmaf(rz, rz, 1e-6f)));
                    float d  = fminf(sqrtf_fast(d2), dclamp);
                    int   k  = (int)(d * inv_h);
                    float4 c = s_tab[k];
                    float phi = fmaf(fmaf(c.z, d, c.y), d, c.x);
                    a0 = fmaf(phi, rx, a0);
                    a1 = fmaf(phi, ry, a1);
                    a2 = fmaf(phi, rz, a2);
                }
            }
            // generic tail (N > 4*TPB): gmem directly
            for (int j = 4 * TPB + tid; j < N; j += TPB) {
                float rx = pix - __ldg(&posb[3 * j + 0]);
                float ry = piy - __ldg(&posb[3 * j + 1]);
                float rz = piz - __ldg(&posb[3 * j + 2]);
                float d2 = fmaf(rx, rx, fmaf(ry, ry, fmaf(rz, rz, 1e-6f)));
                float d  = fminf(sqrtf_fast(d2), dclamp);
                int   k  = (int)(d * inv_h);
                float4 c = s_tab[k];
                float phi = fmaf(fmaf(c.z, d, c.y), d, c.x);
                a0 = fmaf(phi, rx, a0);
                a1 = fmaf(phi, ry, a1);
                a2 = fmaf(phi, rz, a2);
            }
#pragma unroll
            for (int off = 16; off > 0; off >>= 1) {
                a0 += __shfl_down_sync(0xFFFFFFFFu, a0, off);
                a1 += __shfl_down_sync(0xFFFFFFFFu, a1, off);
                a2 += __shfl_down_sync(0xFFFFFFFFu, a2, off);
            }
            if (lane == 0) {
                s_part[pr][warp][0] = a0;
                s_part[pr][warp][1] = a1;
                s_part[pr][warp][2] = a2;
            }
        }
        __syncthreads();

        if (tid < prn) {
            int i = s_rows[p0 + tid];
            float r0 = 0.f, r1 = 0.f, r2 = 0.f;
#pragma unroll
            for (int w = 0; w < NWARPS; w++) {
                r0 += s_part[tid][w][0];
                r1 += s_part[tid][w][1];
                r2 += s_part[tid][w][2];
            }
            size_t o = ((size_t)b * N + i) * 3;
            out[o + 0] = r0 + __ldg(&posb[3 * i + 0]);
            out[o + 1] = r1 + __ldg(&posb[3 * i + 1]);
            out[o + 2] = r2 + __ldg(&posb[3 * i + 2]);
        }
        __syncthreads();   // s_part reused next pass
    }
}

// ---------------------------------------------------------------------------
// Inputs (metadata order):
//  0 positions [B,N,3] f32, 1 t [B] f32, 2 z [N] i32, 3 emb [MAXZ,A] f32,
//  4 W [A,R] f32, 5 rad_off [R], 6 rad_wid [R], 7 time_off [A], 8 time_wid [A]
// ---------------------------------------------------------------------------
extern "C" void kernel_launch(void* const* d_in, const int* in_sizes, int n_in,
                              void* d_out, int out_size) {
    const float* positions = (const float*)d_in[0];
    const float* t         = (const float*)d_in[1];
    const int*   z         = (const int*)  d_in[2];
    const float* emb       = (const float*)d_in[3];
    const float* W         = (const float*)d_in[4];
    const float* r_off     = (const float*)d_in[5];
    const float* r_wid     = (const float*)d_in[6];
    const float* t_off     = (const float*)d_in[7];
    const float* t_wid     = (const float*)d_in[8];

    int B    = in_sizes[1];
    int N    = in_sizes[2];
    int R    = in_sizes[5];
    int A    = in_sizes[7];
    int MAXZ = in_sizes[3] / A;

    int grid = B * MAXZ * SLICES;

    if (R == 50)
        vf_fused_kernel<50><<<grid, TPB>>>(
            positions, z, t, emb, W, r_off, r_wid, t_off, t_wid,
            (float*)d_out, N, A, R, MAXZ);
    else
        vf_fused_kernel<0><<<grid, TPB>>>(
            positions, z, t, emb, W, r_off, r_wid, t_off, t_wid,
            (float*)d_out, N, A, R, MAXZ);
}

// round 12
// speedup vs baseline: 1.2490x; 1.0253x over previous
#include <cuda_runtime.h>
#include <cuda_bf16.h>

// ---------------------------------------------------------------------------
// Single fused kernel. One block of 256 threads per (batch b, type v, slice):
//   - scan slice's i-range for rows with z_i == v
//   - prefactor pref[r] = sum_a emb[v,a]*time_rbf(t_b,a)*W[a,r]
//   - sample phi(d) at 2*KNOTS+1 points, fit piecewise quadratic
//     (global form A + B*d + C*d^2) into a small smem table
//   - pair phase: each thread holds 4 j-positions in REGISTERS loaded
//     directly from gmem; block-wide row loop, warp-shfl reduce +
//     fixed-order 8-partial combine (deterministic)
// FASTN template path: N == 4*TPB exactly -> no tail loop, no j predication.
// All shfls executed unconditionally by whole warps (R10 postmortem).
// ---------------------------------------------------------------------------
#define KNOTS  32
#define DMAXF  16.0f
#define SLICES 4
#define TPB    256
#define NWARPS (TPB / 32)
#define RPASS  8
#define MAXROWS 128

__device__ __forceinline__ float ex2f_fast(float x) {
    float y; asm("ex2.approx.ftz.f32 %0, %1;" : "=f"(y) : "f"(x)); return y;
}
__device__ __forceinline__ float sqrtf_fast(float x) {
    float y; asm("sqrt.approx.f32 %0, %1;" : "=f"(y) : "f"(x)); return y;
}

template <int RR, bool FASTN>
__global__ __launch_bounds__(TPB, 6)
void vf_fused_kernel(const float* __restrict__ pos,
                     const int*   __restrict__ z,
                     const float* __restrict__ t,
                     const float* __restrict__ emb,
                     const float* __restrict__ W,
                     const float* __restrict__ r_off,
                     const float* __restrict__ r_wid,
                     const float* __restrict__ t_off,
                     const float* __restrict__ t_wid,
                     float*       __restrict__ out,
                     int N, int A, int R, int MAXZ) {
    __shared__ float4 s_tab[KNOTS];
    __shared__ float  s_phi[2 * KNOTS + 1];
    __shared__ float  sx[128];
    __shared__ float  s_pref[64], s_k2[64], s_off[64];
    __shared__ int    s_rows[MAXROWS];
    __shared__ float  s_part[RPASS][NWARPS][3];
    __shared__ int    s_count;

    const float LOG2E = 1.4426950408889634f;
    int bvs   = blockIdx.x;
    int bv    = bvs / SLICES;
    int slice = bvs % SLICES;
    int b     = bv / MAXZ;
    int v     = bv % MAXZ;
    int tid   = threadIdx.x;
    int Ruse  = (RR > 0) ? RR : R;
    int Rpad  = (Ruse + 3) & ~3;

    if (tid == 0) s_count = 0;
    __syncthreads();

    const float* posb = pos + (size_t)b * N * 3;

    // ---- scan slice's i-range + param prep (one phase) ----
    int lo = (int)(((long long)N * slice) / SLICES);
    int hi = (int)(((long long)N * (slice + 1)) / SLICES);
    for (int i = lo + tid; i < hi; i += TPB) {
        if (__ldg(&z[i]) == v) {
            int idx = atomicAdd(&s_count, 1);
            if (idx < MAXROWS) s_rows[idx] = i;
        }
    }
    if (tid < A && tid < 128) {
        float tw = t_wid[tid];
        float dt = t[b] - t_off[tid];
        float c  = (-0.5f / (tw * tw)) * LOG2E;
        sx[tid] = emb[(size_t)v * A + tid] * ex2f_fast(c * dt * dt);
    }
    if (tid < 64) {
        if (tid < Ruse) {
            float w = r_wid[tid];
            s_k2[tid]  = (-0.5f / (w * w)) * LOG2E;
            s_off[tid] = r_off[tid];
        } else {
            s_k2[tid]  = -1.0f;     // padding: pref stays 0 -> inert
            s_off[tid] = 0.0f;
            s_pref[tid] = 0.0f;
        }
    }
    __syncthreads();

    int count = s_count;
    if (count == 0) return;          // uniform across block
    if (count > MAXROWS) count = MAXROWS;

    // ---- this thread's 4 j-positions from gmem (coalesced float4 x3) ----
    float jpx[4], jpy[4], jpz[4];
    if (FASTN) {
        int base = tid * 12;
        float4 q0 = __ldg((const float4*)(posb + base));
        float4 q1 = __ldg((const float4*)(posb + base + 4));
        float4 q2 = __ldg((const float4*)(posb + base + 8));
        jpx[0] = q0.x; jpy[0] = q0.y; jpz[0] = q0.z;
        jpx[1] = q0.w; jpy[1] = q1.x; jpz[1] = q1.y;
        jpx[2] = q1.z; jpy[2] = q1.w; jpz[2] = q2.x;
        jpx[3] = q2.y; jpy[3] = q2.z; jpz[3] = q2.w;
    } else {
#pragma unroll
        for (int q = 0; q < 4; q++) {
            int j = 4 * tid + q;
            int jj = (j < N) ? j : 0;
            jpx[q] = __ldg(&posb[3 * jj + 0]);
            jpy[q] = __ldg(&posb[3 * jj + 1]);
            jpz[q] = __ldg(&posb[3 * jj + 2]);
        }
    }

    // ---- prefactor: 4 threads per r (whole warps run the shfls) ----
    {
        int rr  = tid >> 2;
        int sub = tid & 3;
        int rc  = (rr < Ruse) ? rr : (Ruse - 1);
        float s = 0.0f;
        for (int a = sub; a < A; a += 4)
            s = fmaf(sx[a], __ldg(&W[(size_t)a * R + rc]), s);
        s += __shfl_xor_sync(0xFFFFFFFFu, s, 1);
        s += __shfl_xor_sync(0xFFFFFFFFu, s, 2);
        if (sub == 0 && rr < Ruse) s_pref[rr] = s;
    }
    __syncthreads();

    // ---- sample phi at 2*KNOTS+1 points ----
    const float hh = DMAXF / (float)KNOTS;
    if (tid < 2 * KNOTS + 1) {
        float d = (float)tid * (0.5f * hh);
        float a0 = 0.f, a1 = 0.f, a2 = 0.f, a3 = 0.f;
#pragma unroll 1
        for (int r = 0; r < Rpad; r += 4) {
            float e0 = d - s_off[r + 0];
            float e1 = d - s_off[r + 1];
            float e2 = d - s_off[r + 2];
            float e3 = d - s_off[r + 3];
            a0 = fmaf(s_pref[r + 0], ex2f_fast(s_k2[r + 0] * e0 * e0), a0);
            a1 = fmaf(s_pref[r + 1], ex2f_fast(s_k2[r + 1] * e1 * e1), a1);
            a2 = fmaf(s_pref[r + 2], ex2f_fast(s_k2[r + 2] * e2 * e2), a2);
            a3 = fmaf(s_pref[r + 3], ex2f_fast(s_k2[r + 3] * e3 * e3), a3);
        }
        s_phi[tid] = (a0 + a1) + (a2 + a3);
    }
    __syncthreads();

    // ---- fit quadratics (global form A + B*d + C*d^2) ----
    if (tid < KNOTS) {
        float y0 = s_phi[2 * tid + 0];
        float ym = s_phi[2 * tid + 1];
        float y1 = s_phi[2 * tid + 2];
        float inv_h = 1.0f / hh;
        float d0 = (float)tid * hh;
        float bl = (4.0f * ym - 3.0f * y0 - y1) * inv_h;
        float cl = 2.0f * (y1 - 2.0f * ym + y0) * (inv_h * inv_h);
        float Cg = cl;
        float Bg = bl - 2.0f * cl * d0;
        float Ag = y0 - bl * d0 + cl * d0 * d0;
        s_tab[tid] = make_float4(Ag, Bg, Cg, 0.0f);
    }
    __syncthreads();

    // ---- pair phase: block-wide per row, j's from registers ----
    const float inv_h  = (float)KNOTS / DMAXF;
    const float dclamp = DMAXF - 0.5f * hh;
    int warp = tid >> 5, lane = tid & 31;

    for (int p0 = 0; p0 < count; p0 += RPASS) {
        int prn = count - p0; if (prn > RPASS) prn = RPASS;

        for (int pr = 0; pr < prn; pr++) {
            int i = s_rows[p0 + pr];
            float pix = __ldg(&posb[3 * i + 0]);
            float piy = __ldg(&posb[3 * i + 1]);
            float piz = __ldg(&posb[3 * i + 2]);

            float a0 = 0.f, a1 = 0.f, a2 = 0.f;
#pragma unroll
            for (int q = 0; q < 4; q++) {
                bool ok = FASTN || (4 * tid + q < N);
                if (ok) {
                    float rx = pix - jpx[q];
                    float ry = piy - jpy[q];
                    float rz = piz - jpz[q];
                    float d2 = fmaf(rx, rx, fmaf(ry, ry, fmaf(rz, rz, 1e-6f)));
                    float d  = fminf(sqrtf_fast(d2), dclamp);
                    int   k  = (int)(d * inv_h);
                    float4 c = s_tab[k];
                    float phi = fmaf(fmaf(c.z, d, c.y), d, c.x);
                    a0 = fmaf(phi, rx, a0);
                    a1 = fmaf(phi, ry, a1);
                    a2 = fmaf(phi, rz, a2);
                }
            }
            if (!FASTN) {
                for (int j = 4 * TPB + tid; j < N; j += TPB) {
                    float rx = pix - __ldg(&posb[3 * j + 0]);
                    float ry = piy - __ldg(&posb[3 * j + 1]);
                    float rz = piz - __ldg(&posb[3 * j + 2]);
                    float d2 = fmaf(rx, rx, fmaf(ry, ry, fmaf(rz, rz, 1e-6f)));
                    float d  = fminf(sqrtf_fast(d2), dclamp);
                    int   k  = (int)(d * inv_h);
                    float4 c = s_tab[k];
                    float phi = fmaf(fmaf(c.z, d, c.y), d, c.x);
                    a0 = fmaf(phi, rx, a0);
                    a1 = fmaf(phi, ry, a1);
                    a2 = fmaf(phi, rz, a2);
                }
            }
#pragma unroll
            for (int off = 16; off > 0; off >>= 1) {
                a0 += __shfl_down_sync(0xFFFFFFFFu, a0, off);
                a1 += __shfl_down_sync(0xFFFFFFFFu, a1, off);
                a2 += __shfl_down_sync(0xFFFFFFFFu, a2, off);
            }
            if (lane == 0) {
                s_part[pr][warp][0] = a0;
                s_part[pr][warp][1] = a1;
                s_part[pr][warp][2] = a2;
            }
        }
        __syncthreads();

        if (tid < prn) {
            int i = s_rows[p0 + tid];
            float r0 = 0.f, r1 = 0.f, r2 = 0.f;
#pragma unroll
            for (int w = 0; w < NWARPS; w++) {
                r0 += s_part[tid][w][0];
                r1 += s_part[tid][w][1];
                r2 += s_part[tid][w][2];
            }
            size_t o = ((size_t)b * N + i) * 3;
            out[o + 0] = r0 + __ldg(&posb[3 * i + 0]);
            out[o + 1] = r1 + __ldg(&posb[3 * i + 1]);
            out[o + 2] = r2 + __ldg(&posb[3 * i + 2]);
        }
        __syncthreads();
    }
}

// ---------------------------------------------------------------------------
// Inputs (metadata order):
//  0 positions [B,N,3] f32, 1 t [B] f32, 2 z [N] i32, 3 emb [MAXZ,A] f32,
//  4 W [A,R] f32, 5 rad_off [R], 6 rad_wid [R], 7 time_off [A], 8 time_wid [A]
// ---------------------------------------------------------------------------
extern "C" void kernel_launch(void* const* d_in, const int* in_sizes, int n_in,
                              void* d_out, int out_size) {
    const float* positions = (const float*)d_in[0];
    const float* t         = (const float*)d_in[1];
    const int*   z         = (const int*)  d_in[2];
    const float* emb       = (const float*)d_in[3];
    const float* W         = (const float*)d_in[4];
    const float* r_off     = (const float*)d_in[5];
    const float* r_wid     = (const float*)d_in[6];
    const float* t_off     = (const float*)d_in[7];
    const float* t_wid     = (const float*)d_in[8];

    int B    = in_sizes[1];
    int N    = in_sizes[2];
    int R    = in_sizes[5];
    int A    = in_sizes[7];
    int MAXZ = in_sizes[3] / A;

    int grid = B * MAXZ * SLICES;
    bool fastn = (N == 4 * TPB) && ((3 * N) % 4 == 0);

    if (R == 50 && fastn)
        vf_fused_kernel<50, true><<<grid, TPB>>>(
            positions, z, t, emb, W, r_off, r_wid, t_off, t_wid,
            (float*)d_out, N, A, R, MAXZ);
    else if (R == 50)
        vf_fused_kernel<50, false><<<grid, TPB>>>(
            positions, z, t, emb, W, r_off, r_wid, t_off, t_wid,
            (float*)d_out, N, A, R, MAXZ);
    else
        vf_fused_kernel<0, false><<<grid, TPB>>>(
            positions, z, t, emb, W, r_off, r_wid, t_off, t_wid,
            (float*)d_out, N, A, R, MAXZ);
}